// round 16
// baseline (speedup 1.0000x reference)
#include <cuda_runtime.h>
#include <cuda_fp16.h>
#include <cstdint>
#include <cstddef>

// Problem constants
#define BB   32
#define TT   1024
#define CC   512
#define KK   3
#define LMAX 4096
#define BT   (BB*TT)
#define LN_EPS 1e-5f

// GEMM tiling (fp16 mma.sync m16n8k16, fp32 accumulate)
#define BM 128
#define BN 256
#define BK 32
#define NSLAB ((KK*CC)/BK)    // 48
#define STG 2

// conv grid: (BT/BM) * (CC/BN) = 256 * 2
#define CONV_BLKS 512
#define REG_BLKS  4096        // BB * (LMAX/32)
// pre-kernel block partition
#define RND_BLKS  16384       // BT*CC/4/256
#define WT_BLKS   1024        // CC*CC/256

// slab layout: 32 halves = 16 k-pairs; pair p stored at halves (p&3)*8 + (p>>2)*2.
__host__ __device__ __forceinline__ int poff(int p) {
    return (p & 3) * 8 + (p >> 2) * 2;
}

// ---------------- scratch (device globals; no allocations allowed) ----------
__device__ __half g_bufA[(size_t)BT * CC];         // fp16 slab-permuted batch
__device__ float  g_buf1[(size_t)BT * CC];         // conv1 out fp32
__device__ __half g_buf1h[(size_t)BT * CC];        // ln(conv1) fp16 slab-permuted
__device__ float  g_buf2[(size_t)BT * CC];         // conv2 out fp32
__device__ __half g_wt[2 * (size_t)KK * CC * CC];  // [set][k][slab16][co][32perm]
__device__ int    g_cum[BB * TT];

// ================= helpers ==================================================
__device__ __forceinline__ uint32_t smem_u32(const void* p) {
    uint32_t r;
    asm("{ .reg .u64 t; cvta.to.shared.u64 t, %1; cvt.u32.u64 %0, t; }"
        : "=r"(r) : "l"(p));
    return r;
}
__device__ __forceinline__ void cp_async16(uint32_t dst, const void* src, bool ok) {
    int sz = ok ? 16 : 0;
    asm volatile("cp.async.ca.shared.global [%0], [%1], 16, %2;"
                 :: "r"(dst), "l"(src), "r"(sz));
}
#define CP_COMMIT() asm volatile("cp.async.commit_group;" ::: "memory")
#define CP_WAIT1()  asm volatile("cp.async.wait_group 1;" ::: "memory")
#define CP_WAIT0()  asm volatile("cp.async.wait_group 0;" ::: "memory")

__device__ __forceinline__ void mma_f16(float* c, uint32_t a0, uint32_t a1,
                                        uint32_t a2, uint32_t a3,
                                        uint32_t b0, uint32_t b1) {
    asm volatile("mma.sync.aligned.m16n8k16.row.col.f32.f16.f16.f32 "
                 "{%0,%1,%2,%3}, {%4,%5,%6,%7}, {%8,%9}, {%0,%1,%2,%3};"
                 : "+f"(c[0]), "+f"(c[1]), "+f"(c[2]), "+f"(c[3])
                 : "r"(a0), "r"(a1), "r"(a2), "r"(a3), "r"(b0), "r"(b1));
}

// write 4 consecutive logical halves (even pair p0, p0+1) into slab storage
__device__ __forceinline__ void store_perm4(__half* sbase, int p0,
                                            float v0, float v1, float v2, float v3)
{
    *(__half2*)(sbase + poff(p0))     = __floats2half2_rn(v0, v1);
    *(__half2*)(sbase + poff(p0 + 1)) = __floats2half2_rn(v2, v3);
}

// ============ PRE: round(batch->fp16 perm) | wt x2 | durations ==============
__global__ void __launch_bounds__(256) pre_kernel(const float4* __restrict__ batch4,
                                                  __half* __restrict__ bufA,
                                                  const float* __restrict__ w1,
                                                  const float* __restrict__ w2,
                                                  __half* __restrict__ wt1,
                                                  __half* __restrict__ wt2,
                                                  const int* __restrict__ durs,
                                                  const int* __restrict__ lens,
                                                  int* __restrict__ cum,
                                                  float* __restrict__ mel)
{
    __shared__ int sred[256];
    __shared__ int sscan[256];
    int bid = blockIdx.x;
    int tid = threadIdx.x;

    if (bid < RND_BLKS) {
        size_t i = (size_t)bid * 256 + tid;
        float4 v = batch4[i];
        int f = (int)(i & 127);            // float4 index within row
        size_t rowbase = (i >> 7) * CC;
        int sl = f >> 3;                   // 32-half slab
        int p0 = (f & 7) * 2;              // even pair index
        store_perm4(bufA + rowbase + sl * 32, p0, v.x, v.y, v.z, v.w);
        return;
    }
    if (bid < RND_BLKS + 2 * WT_BLKS) {
        int wb = bid - RND_BLKS;
        const float* w = (wb < WT_BLKS) ? w1 : w2;
        __half* wt = (wb < WT_BLKS) ? wt1 : wt2;
        int idx = (wb & (WT_BLKS - 1)) * 256 + tid;
        int co = idx >> 9;
        int ci = idx & (CC - 1);
        int sl = ci >> 5;
        int p  = (ci >> 1) & 15;
        int pos = poff(p) + (ci & 1);
#pragma unroll
        for (int k = 0; k < KK; k++)
            wt[(((size_t)k * 16 + sl) * CC + co) * 32 + pos] =
                __float2half_rn(w[((size_t)co * CC + ci) * KK + k]);
        return;
    }
    {
        int b   = bid - (RND_BLKS + 2 * WT_BLKS);
        int len = lens[b];
        int base = tid * 4;
        const int* drow = durs + (size_t)b * TT;

        int d[4];
#pragma unroll
        for (int j = 0; j < 4; j++)
            d[j] = (base + j < len) ? drow[base + j] : 0;
        int ls = d[0] + d[1] + d[2] + d[3];

        sred[tid] = ls;
        __syncthreads();
        for (int o = 128; o > 0; o >>= 1) {
            if (tid < o) sred[tid] += sred[tid + o];
            __syncthreads();
        }
        int total = sred[0];
        __syncthreads();

        if (total == 0) {
#pragma unroll
            for (int j = 0; j < 4; j++)
                d[j] = (base + j < len) ? 1 : 0;
            ls = d[0] + d[1] + d[2] + d[3];
        }

        sscan[tid] = ls;
        __syncthreads();
        for (int o = 1; o < 256; o <<= 1) {
            int v = (tid >= o) ? sscan[tid - o] : 0;
            __syncthreads();
            sscan[tid] += v;
            __syncthreads();
        }
        int c = sscan[tid] - ls;
#pragma unroll
        for (int j = 0; j < 4; j++) {
            c += d[j];
            cum[(size_t)b * TT + base + j] = c;
        }
        if (tid == 255) mel[b] = (float)c;
    }
}

// ======= conv tile body: 8 warps (2x4), warp tile 64x64, BK=32, STG=2 =======
// smem rows are 64B; 16B-chunk q of row r stored at q ^ (r&2).  48KB static.
struct ConvSmem {
    __half As[STG][BM][BK];    // 16 KB
    __half Bs[STG][BN][BK];    // 32 KB
};

__device__ __forceinline__ void conv_tile(ConvSmem* sm,
                                          const __half* __restrict__ A,
                                          const __half* __restrict__ Wt,
                                          const float* __restrict__ bias,
                                          float* __restrict__ out,
                                          int m0, int n0)
{
    int tid  = threadIdx.x;
    int wid  = tid >> 5;
    int lane = tid & 31;
    int warp_m = wid & 1;        // 2 warps in M (64 rows each)
    int warp_n = wid >> 1;       // 4 warps in N (64 cols each)
    int gid = lane >> 2;         // 0..7
    int tig = lane & 3;          // 0..3
    int cw  = (tig ^ (gid & 2)) * 8;   // halves offset of this lane's 16B chunk

    int b  = m0 >> 10;
    int t0 = m0 & 1023;
    const __half* Ab = A + (size_t)b * TT * CC;

    float c[4][8][4];
#pragma unroll
    for (int mt = 0; mt < 4; mt++)
#pragma unroll
        for (int nt = 0; nt < 8; nt++)
#pragma unroll
            for (int q = 0; q < 4; q++) c[mt][nt][q] = 0.f;

    // A loader: tid>>1 = row 0..127, tid&1 = 32B half; B loader: tid = row 0..255
    int lrow  = tid >> 1;
    int lhalf = tid & 1;

    auto load_slab = [&](int s, int st) {
        int k  = s >> 4;               // conv tap 0..2 (16 slabs per tap)
        int sl = s & 15;               // slab index within tap
        // A: 2 chunks per thread
        int strow = t0 + lrow + k - 1;
        bool ok = (strow >= 0 && strow < TT);
        const __half* asrc = Ab + (ok ? (size_t)strow * CC : 0) + sl * 32 + lhalf * 16;
#pragma unroll
        for (int q2 = 0; q2 < 2; q2++) {
            int q  = lhalf * 2 + q2;
            int dq = q ^ (lrow & 2);
            cp_async16(smem_u32(&sm->As[st][lrow][dq * 8]), asrc + q2 * 8, ok);
        }
        // B: 4 chunks per thread (one full 64B row)
        const __half* bsrc = Wt + (((size_t)k * 16 + sl) * CC + n0 + tid) * 32;
#pragma unroll
        for (int q = 0; q < 4; q++) {
            int dq = q ^ (tid & 2);
            cp_async16(smem_u32(&sm->Bs[st][tid][dq * 8]), bsrc + q * 8, true);
        }
    };

    load_slab(0, 0); CP_COMMIT();

    for (int s = 0; s < NSLAB; s++) {
        int st = s & 1;
        if (s + 1 < NSLAB) {
            load_slab(s + 1, (s + 1) & 1);
            CP_COMMIT();
            CP_WAIT1();                // slab s resident
        } else {
            CP_WAIT0();
        }
        __syncthreads();

        // B panel once (8 LDS.128), then per-mt A (2 LDS.128) -> 16 MMAs
        uint4 b4[8];
#pragma unroll
        for (int nt = 0; nt < 8; nt++) {
            int nc = warp_n * 64 + nt * 8 + gid;
            b4[nt] = *(const uint4*)&sm->Bs[st][nc][cw];
        }
#pragma unroll
        for (int mt = 0; mt < 4; mt++) {
            int mr = warp_m * 64 + mt * 16;
            uint4 alo = *(const uint4*)&sm->As[st][mr + gid    ][cw];
            uint4 ahi = *(const uint4*)&sm->As[st][mr + gid + 8][cw];
#pragma unroll
            for (int nt = 0; nt < 8; nt++) {
                mma_f16(c[mt][nt], alo.x, ahi.x, alo.y, ahi.y, b4[nt].x, b4[nt].y);
                mma_f16(c[mt][nt], alo.z, ahi.z, alo.w, ahi.w, b4[nt].z, b4[nt].w);
            }
        }
        __syncthreads();               // stage consumed before next overwrite
    }

    // epilogue: bias + relu, coalesced stores
#pragma unroll
    for (int mt = 0; mt < 4; mt++) {
        int row = m0 + warp_m * 64 + mt * 16 + gid;
#pragma unroll
        for (int nt = 0; nt < 8; nt++) {
            int col = n0 + warp_n * 64 + nt * 8 + tig * 2;
            float b0 = __ldg(&bias[col]);
            float b1 = __ldg(&bias[col + 1]);
            float2 v0, v1;
            v0.x = fmaxf(c[mt][nt][0] + b0, 0.f);
            v0.y = fmaxf(c[mt][nt][1] + b1, 0.f);
            v1.x = fmaxf(c[mt][nt][2] + b0, 0.f);
            v1.y = fmaxf(c[mt][nt][3] + b1, 0.f);
            *(float2*)&out[(size_t)row * CC + col]       = v0;
            *(float2*)&out[(size_t)(row + 8) * CC + col] = v1;
        }
    }
}

// ============ MEGA: conv1 (blocks [0,512)) | regulate (rest) ================
__global__ void __launch_bounds__(256, 1) mega_kernel(const __half* __restrict__ A,
                                                      const __half* __restrict__ Wt,
                                                      const float* __restrict__ bias,
                                                      float* __restrict__ out,
                                                      const float* __restrict__ batch,
                                                      const int* __restrict__ cum,
                                                      float* __restrict__ padded)
{
    __shared__ ConvSmem sm;            // 48KB static; sc overlays it in reg branch
    int tid = threadIdx.x;

    if (blockIdx.x < CONV_BLKS) {
        int m0 = (blockIdx.x >> 1) * BM;
        int n0 = (blockIdx.x & 1) * BN;
        conv_tile(&sm, A, Wt, bias, out, m0, n0);
    } else {
        int* sc = (int*)&sm;           // 4KB overlay (disjoint branch)
        int r  = blockIdx.x - CONV_BLKS;
        int b  = r >> 7;
        int f0 = (r & 127) * 32;
        const int* crow = cum + (size_t)b * TT;
#pragma unroll
        for (int j = 0; j < 4; j++) sc[tid + 256 * j] = crow[tid + 256 * j];
        __syncthreads();
        int total = sc[TT - 1];
        int warp = tid >> 5, lane = tid & 31;
        float* outb = padded + (size_t)b * LMAX * CC;
        const float* inb = batch + (size_t)b * TT * CC;
#pragma unroll
        for (int qq = 0; qq < 4; qq++) {
            int f = f0 + warp * 4 + qq;
            float4* dst = (float4*)(outb + (size_t)f * CC);
            if (f < total) {
                int lo = 0, hi = TT;
                while (lo < hi) {
                    int mid = (lo + hi) >> 1;
                    if (sc[mid] <= f) lo = mid + 1; else hi = mid;
                }
                const float4* src = (const float4*)(inb + (size_t)lo * CC);
#pragma unroll
                for (int u = 0; u < 4; u++) dst[lane + 32 * u] = src[lane + 32 * u];
            } else {
                float4 z = make_float4(0.f, 0.f, 0.f, 0.f);
#pragma unroll
                for (int u = 0; u < 4; u++) dst[lane + 32 * u] = z;
            }
        }
    }
}

// ---------------- conv2: plain conv-as-GEMM ---------------------------------
__global__ void __launch_bounds__(256, 1) conv_mma_kernel(const __half* __restrict__ A,
                                                          const __half* __restrict__ Wt,
                                                          const float* __restrict__ bias,
                                                          float* __restrict__ out)
{
    __shared__ ConvSmem sm;
    conv_tile(&sm, A, Wt, bias, out,
              (blockIdx.x >> 1) * BM, (blockIdx.x & 1) * BN);
}

// ---------------- LayerNorm over C=512, one block per row -------------------
// Reads fp32 normal order, writes fp16 slab-permuted (input to conv2).
__global__ void __launch_bounds__(128) ln_kernel(const float* __restrict__ x,
                                                 const float* __restrict__ g,
                                                 const float* __restrict__ beta,
                                                 __half* __restrict__ xo)
{
    size_t row = blockIdx.x;
    const float4* xr = (const float4*)(x + row * CC);
    int tid = threadIdx.x;
    float4 v = xr[tid];
    float s = v.x + v.y + v.z + v.w;
    float q = v.x * v.x + v.y * v.y + v.z * v.z + v.w * v.w;
#pragma unroll
    for (int o = 16; o > 0; o >>= 1) {
        s += __shfl_xor_sync(0xffffffffu, s, o);
        q += __shfl_xor_sync(0xffffffffu, q, o);
    }
    __shared__ float ss[4], sq[4];
    int w = tid >> 5, l = tid & 31;
    if (l == 0) { ss[w] = s; sq[w] = q; }
    __syncthreads();
    s = ss[0] + ss[1] + ss[2] + ss[3];
    q = sq[0] + sq[1] + sq[2] + sq[3];
    float mean = s * (1.f / CC);
    float var  = q * (1.f / CC) - mean * mean;
    float r = rsqrtf(var + LN_EPS);
    float4 gv = ((const float4*)g)[tid];
    float4 bv = ((const float4*)beta)[tid];
    float o0 = (v.x - mean) * r * gv.x + bv.x;
    float o1 = (v.y - mean) * r * gv.y + bv.y;
    float o2 = (v.z - mean) * r * gv.z + bv.z;
    float o3 = (v.w - mean) * r * gv.w + bv.w;
    int sl = tid >> 3;
    int p0 = (tid & 7) * 2;
    store_perm4(xo + row * CC + sl * 32, p0, o0, o1, o2, o3);
}

// ---------------- LN + Linear(C->1) + mask, one block per row ---------------
__global__ void __launch_bounds__(128) ln_lin_kernel(const float* __restrict__ x,
                                                     const float* __restrict__ g,
                                                     const float* __restrict__ beta,
                                                     const float* __restrict__ lw,
                                                     const float* __restrict__ lb,
                                                     const int* __restrict__ lens,
                                                     float* __restrict__ pred)
{
    size_t row = blockIdx.x;
    const float4* xr = (const float4*)(x + row * CC);
    int tid = threadIdx.x;
    float4 v = xr[tid];
    float s = v.x + v.y + v.z + v.w;
    float q = v.x * v.x + v.y * v.y + v.z * v.z + v.w * v.w;
#pragma unroll
    for (int o = 16; o > 0; o >>= 1) {
        s += __shfl_xor_sync(0xffffffffu, s, o);
        q += __shfl_xor_sync(0xffffffffu, q, o);
    }
    __shared__ float ss[4], sq[4], sp[4];
    int w = tid >> 5, l = tid & 31;
    if (l == 0) { ss[w] = s; sq[w] = q; }
    __syncthreads();
    s = ss[0] + ss[1] + ss[2] + ss[3];
    q = sq[0] + sq[1] + sq[2] + sq[3];
    float mean = s * (1.f / CC);
    float var  = q * (1.f / CC) - mean * mean;
    float r = rsqrtf(var + LN_EPS);
    float4 gv = ((const float4*)g)[tid];
    float4 bv = ((const float4*)beta)[tid];
    float4 wv = ((const float4*)lw)[tid];
    float part = ((v.x - mean) * r * gv.x + bv.x) * wv.x
               + ((v.y - mean) * r * gv.y + bv.y) * wv.y
               + ((v.z - mean) * r * gv.z + bv.z) * wv.z
               + ((v.w - mean) * r * gv.w + bv.w) * wv.w;
#pragma unroll
    for (int o = 16; o > 0; o >>= 1)
        part += __shfl_xor_sync(0xffffffffu, part, o);
    if (l == 0) sp[w] = part;
    __syncthreads();
    if (tid == 0) {
        float val = sp[0] + sp[1] + sp[2] + sp[3] + lb[0];
        int b = (int)(row >> 10);
        int t = (int)(row & 1023);
        pred[row] = (t < lens[b]) ? val : 0.f;
    }
}

// ---------------- launch --------------------------------------------------
extern "C" void kernel_launch(void* const* d_in, const int* in_sizes, int n_in,
                              void* d_out, int out_size)
{
    const float* batch = (const float*)d_in[0];
    const int*   lens  = (const int*)d_in[1];
    const int*   durs  = (const int*)d_in[3];
    const float* w1    = (const float*)d_in[4];
    const float* b1    = (const float*)d_in[5];
    const float* g1    = (const float*)d_in[6];
    const float* be1   = (const float*)d_in[7];
    const float* w2    = (const float*)d_in[8];
    const float* b2    = (const float*)d_in[9];
    const float* g2    = (const float*)d_in[10];
    const float* be2   = (const float*)d_in[11];
    const float* lw    = (const float*)d_in[12];
    const float* lb    = (const float*)d_in[13];

    float* out    = (float*)d_out;
    float* padded = out;
    float* mel    = out + (size_t)BB * LMAX * CC;
    float* pred   = mel + BB;

    __half *bufA, *buf1h, *wt;
    float  *buf1, *buf2;
    int    *cum;
    cudaGetSymbolAddress((void**)&bufA,  g_bufA);
    cudaGetSymbolAddress((void**)&buf1,  g_buf1);
    cudaGetSymbolAddress((void**)&buf1h, g_buf1h);
    cudaGetSymbolAddress((void**)&buf2,  g_buf2);
    cudaGetSymbolAddress((void**)&wt,    g_wt);
    cudaGetSymbolAddress((void**)&cum,   g_cum);
    __half* wt2 = wt + (size_t)KK * CC * CC;

    pre_kernel<<<RND_BLKS + 2 * WT_BLKS + BB, 256>>>(
        (const float4*)batch, bufA, w1, w2, wt, wt2, durs, lens, cum, mel);

    mega_kernel<<<CONV_BLKS + REG_BLKS, 256>>>(
        bufA, wt, b1, buf1, batch, cum, padded);

    ln_kernel<<<BT, 128>>>(buf1, g1, be1, buf1h);
    conv_mma_kernel<<<CONV_BLKS, 256>>>(buf1h, wt2, b2, buf2);
    ln_lin_kernel<<<BT, 128>>>(buf2, g2, be2, lw, lb, lens, pred);
}

// round 17
// speedup vs baseline: 1.3145x; 1.3145x over previous
#include <cuda_runtime.h>
#include <cuda_fp16.h>
#include <cstdint>
#include <cstddef>

// Problem constants
#define BB   32
#define TT   1024
#define CC   512
#define KK   3
#define LMAX 4096
#define BT   (BB*TT)
#define LN_EPS 1e-5f

// GEMM tiling (fp16 mma.sync m16n8k16, fp32 accumulate)
#define BM 128
#define BN 128
#define BK 32
#define NSLAB ((KK*CC)/BK)    // 48
#define STG 3

// mega-kernel block partition
#define CONV_BLKS 1024        // (BT/BM) * (CC/BN)
#define REG_BLKS  4096        // BB * (LMAX/32)
// pre-kernel block partition
#define RND_BLKS  16384       // BT*CC/4/256
#define WT_BLKS   1024        // CC*CC/256

// slab layout: 32 halves = 16 k-pairs; pair p stored at halves (p&3)*8 + (p>>2)*2.
__host__ __device__ __forceinline__ int poff(int p) {
    return (p & 3) * 8 + (p >> 2) * 2;
}

// ---------------- scratch (device globals; no allocations allowed) ----------
__device__ __half g_bufA[(size_t)BT * CC];         // fp16 slab-permuted batch
__device__ float  g_buf1[(size_t)BT * CC];         // conv1 out fp32
__device__ __half g_buf1h[(size_t)BT * CC];        // ln(conv1) fp16 slab-permuted
__device__ float  g_part[(size_t)BT * 16];         // conv2 LN partials [row][nb][4]
__device__ __half g_wt[2 * (size_t)KK * CC * CC];  // [set][k][slab16][co][32perm]
__device__ int    g_cum[BB * TT];
__device__ float  g_gw[CC];                        // g2*lw
__device__ float  g_sc[2];                         // {sgw, sbw}

// ================= helpers ==================================================
__device__ __forceinline__ uint32_t smem_u32(const void* p) {
    uint32_t r;
    asm("{ .reg .u64 t; cvta.to.shared.u64 t, %1; cvt.u32.u64 %0, t; }"
        : "=r"(r) : "l"(p));
    return r;
}
__device__ __forceinline__ void cp_async16(uint32_t dst, const void* src, bool ok) {
    int sz = ok ? 16 : 0;
    asm volatile("cp.async.ca.shared.global [%0], [%1], 16, %2;"
                 :: "r"(dst), "l"(src), "r"(sz));
}
#define CP_COMMIT() asm volatile("cp.async.commit_group;" ::: "memory")
#define CP_WAIT1()  asm volatile("cp.async.wait_group 1;" ::: "memory")

__device__ __forceinline__ void mma_f16(float* c, uint32_t a0, uint32_t a1,
                                        uint32_t a2, uint32_t a3,
                                        uint32_t b0, uint32_t b1) {
    asm volatile("mma.sync.aligned.m16n8k16.row.col.f32.f16.f16.f32 "
                 "{%0,%1,%2,%3}, {%4,%5,%6,%7}, {%8,%9}, {%0,%1,%2,%3};"
                 : "+f"(c[0]), "+f"(c[1]), "+f"(c[2]), "+f"(c[3])
                 : "r"(a0), "r"(a1), "r"(a2), "r"(a3), "r"(b0), "r"(b1));
}

// write 4 consecutive logical halves (even pair p0, p0+1) into slab storage
__device__ __forceinline__ void store_perm4(__half* sbase, int p0,
                                            float v0, float v1, float v2, float v3)
{
    *(__half2*)(sbase + poff(p0))     = __floats2half2_rn(v0, v1);
    *(__half2*)(sbase + poff(p0 + 1)) = __floats2half2_rn(v2, v3);
}

// ==== PRE: round(batch) | wt x2 | durations | gw/sgw/sbw ====================
__global__ void __launch_bounds__(256) pre_kernel(const float4* __restrict__ batch4,
                                                  __half* __restrict__ bufA,
                                                  const float* __restrict__ w1,
                                                  const float* __restrict__ w2,
                                                  __half* __restrict__ wt1,
                                                  __half* __restrict__ wt2,
                                                  const int* __restrict__ durs,
                                                  const int* __restrict__ lens,
                                                  int* __restrict__ cum,
                                                  float* __restrict__ mel,
                                                  const float* __restrict__ g2,
                                                  const float* __restrict__ be2,
                                                  const float* __restrict__ lw,
                                                  float* __restrict__ gw,
                                                  float* __restrict__ sc)
{
    __shared__ int sred[256];
    __shared__ int sscan[256];
    __shared__ float sfl[16];
    int bid = blockIdx.x;
    int tid = threadIdx.x;

    if (bid < RND_BLKS) {
        size_t i = (size_t)bid * 256 + tid;
        float4 v = batch4[i];
        int f = (int)(i & 127);            // float4 index within row
        size_t rowbase = (i >> 7) * CC;
        int sl = f >> 3;                   // 32-half slab
        int p0 = (f & 7) * 2;              // even pair index
        store_perm4(bufA + rowbase + sl * 32, p0, v.x, v.y, v.z, v.w);
        return;
    }
    if (bid < RND_BLKS + 2 * WT_BLKS) {
        int wb = bid - RND_BLKS;
        const float* w = (wb < WT_BLKS) ? w1 : w2;
        __half* wt = (wb < WT_BLKS) ? wt1 : wt2;
        int idx = (wb & (WT_BLKS - 1)) * 256 + tid;
        int co = idx >> 9;
        int ci = idx & (CC - 1);
        int sl = ci >> 5;
        int p  = (ci >> 1) & 15;
        int pos = poff(p) + (ci & 1);
#pragma unroll
        for (int k = 0; k < KK; k++)
            wt[(((size_t)k * 16 + sl) * CC + co) * 32 + pos] =
                __float2half_rn(w[((size_t)co * CC + ci) * KK + k]);
        return;
    }
    if (bid < RND_BLKS + 2 * WT_BLKS + BB) {
        int b   = bid - (RND_BLKS + 2 * WT_BLKS);
        int len = lens[b];
        int base = tid * 4;
        const int* drow = durs + (size_t)b * TT;

        int d[4];
#pragma unroll
        for (int j = 0; j < 4; j++)
            d[j] = (base + j < len) ? drow[base + j] : 0;
        int ls = d[0] + d[1] + d[2] + d[3];

        sred[tid] = ls;
        __syncthreads();
        for (int o = 128; o > 0; o >>= 1) {
            if (tid < o) sred[tid] += sred[tid + o];
            __syncthreads();
        }
        int total = sred[0];
        __syncthreads();

        if (total == 0) {
#pragma unroll
            for (int j = 0; j < 4; j++)
                d[j] = (base + j < len) ? 1 : 0;
            ls = d[0] + d[1] + d[2] + d[3];
        }

        sscan[tid] = ls;
        __syncthreads();
        for (int o = 1; o < 256; o <<= 1) {
            int v = (tid >= o) ? sscan[tid - o] : 0;
            __syncthreads();
            sscan[tid] += v;
            __syncthreads();
        }
        int c = sscan[tid] - ls;
#pragma unroll
        for (int j = 0; j < 4; j++) {
            c += d[j];
            cum[(size_t)b * TT + base + j] = c;
        }
        if (tid == 255) mel[b] = (float)c;
        return;
    }
    {
        // gw = g2*lw; sgw = sum(g2*lw); sbw = sum(be2*lw)
        float a1 = 0.f, a2 = 0.f;
        for (int i = tid; i < CC; i += 256) {
            float gv = g2[i], wv = lw[i], bv = be2[i];
            gw[i] = gv * wv;
            a1 += gv * wv;
            a2 += bv * wv;
        }
#pragma unroll
        for (int o = 16; o > 0; o >>= 1) {
            a1 += __shfl_xor_sync(0xffffffffu, a1, o);
            a2 += __shfl_xor_sync(0xffffffffu, a2, o);
        }
        int w8 = tid >> 5, l = tid & 31;
        if (l == 0) { sfl[w8] = a1; sfl[w8 + 8] = a2; }
        __syncthreads();
        if (tid == 0) {
            float t1 = 0.f, t2 = 0.f;
            for (int j = 0; j < 8; j++) { t1 += sfl[j]; t2 += sfl[j + 8]; }
            sc[0] = t1; sc[1] = t2;
        }
    }
}

// ======= conv tile body: 8 warps (2x4), warp tile 64x32, BK=32 ==============
// smem rows are 64B; 16B-chunk q of row r stored at q ^ (r&2).
struct ConvSmem {
    __half As[STG][BM][BK];
    __half Bs[STG][BN][BK];
};

// FUSE=false: write out (bias+relu). FUSE=true: emit LN partials to part.
template<bool FUSE>
__device__ __forceinline__ void conv_tile(ConvSmem* sm,
                                          const __half* __restrict__ A,
                                          const __half* __restrict__ Wt,
                                          const float* __restrict__ bias,
                                          float* __restrict__ out,
                                          const float* __restrict__ gw,
                                          float* __restrict__ part,
                                          int m0, int n0)
{
    int tid  = threadIdx.x;
    int wid  = tid >> 5;
    int lane = tid & 31;
    int warp_m = wid & 1;        // 2 warps in M (64 rows each)
    int warp_n = wid >> 1;       // 4 warps in N (32 cols each)
    int gid = lane >> 2;         // 0..7
    int tig = lane & 3;          // 0..3
    int cw  = (tig ^ (gid & 2)) * 8;   // halves offset of this lane's 16B chunk

    int b  = m0 >> 10;
    int t0 = m0 & 1023;
    const __half* Ab = A + (size_t)b * TT * CC;

    float c[4][4][4];
#pragma unroll
    for (int mt = 0; mt < 4; mt++)
#pragma unroll
        for (int nt = 0; nt < 4; nt++)
#pragma unroll
            for (int q = 0; q < 4; q++) c[mt][nt][q] = 0.f;

    // loader: tid>>1 = row 0..127, tid&1 = which 32B half of the 64B slab row
    int lrow  = tid >> 1;
    int lhalf = tid & 1;

    auto load_slab = [&](int s, int st) {
        int k  = s >> 4;               // conv tap 0..2 (16 slabs per tap)
        int sl = s & 15;               // slab index within tap
        int strow = t0 + lrow + k - 1;
        bool ok = (strow >= 0 && strow < TT);
        const __half* asrc = Ab + (ok ? (size_t)strow * CC : 0) + sl * 32 + lhalf * 16;
        const __half* bsrc = Wt + (((size_t)k * 16 + sl) * CC + n0 + lrow) * 32 + lhalf * 16;
#pragma unroll
        for (int q2 = 0; q2 < 2; q2++) {
            int q  = lhalf * 2 + q2;
            int dq = q ^ (lrow & 2);
            cp_async16(smem_u32(&sm->As[st][lrow][dq * 8]), asrc + q2 * 8, ok);
            cp_async16(smem_u32(&sm->Bs[st][lrow][dq * 8]), bsrc + q2 * 8, true);
        }
    };

    load_slab(0, 0); CP_COMMIT();
    load_slab(1, 1); CP_COMMIT();

    for (int s = 0; s < NSLAB; s++) {
        int st = s % STG;
        CP_WAIT1();
        __syncthreads();
        if (s + 2 < NSLAB) load_slab(s + 2, (s + 2) % STG);
        CP_COMMIT();

        uint4 b4[4];
#pragma unroll
        for (int nt = 0; nt < 4; nt++) {
            int nc = warp_n * 32 + nt * 8 + gid;
            b4[nt] = *(const uint4*)&sm->Bs[st][nc][cw];
        }
#pragma unroll
        for (int mt = 0; mt < 4; mt++) {
            int mr = warp_m * 64 + mt * 16;
            uint4 alo = *(const uint4*)&sm->As[st][mr + gid    ][cw];
            uint4 ahi = *(const uint4*)&sm->As[st][mr + gid + 8][cw];
#pragma unroll
            for (int nt = 0; nt < 4; nt++) {
                mma_f16(c[mt][nt], alo.x, ahi.x, alo.y, ahi.y, b4[nt].x, b4[nt].y);
                mma_f16(c[mt][nt], alo.z, ahi.z, alo.w, ahi.w, b4[nt].z, b4[nt].w);
            }
        }
    }

    if (!FUSE) {
        // epilogue: bias + relu, coalesced stores
#pragma unroll
        for (int mt = 0; mt < 4; mt++) {
            int row = m0 + warp_m * 64 + mt * 16 + gid;
#pragma unroll
            for (int nt = 0; nt < 4; nt++) {
                int col = n0 + warp_n * 32 + nt * 8 + tig * 2;
                float b0 = __ldg(&bias[col]);
                float b1 = __ldg(&bias[col + 1]);
                float2 v0, v1;
                v0.x = fmaxf(c[mt][nt][0] + b0, 0.f);
                v0.y = fmaxf(c[mt][nt][1] + b1, 0.f);
                v1.x = fmaxf(c[mt][nt][2] + b0, 0.f);
                v1.y = fmaxf(c[mt][nt][3] + b1, 0.f);
                *(float2*)&out[(size_t)row * CC + col]       = v0;
                *(float2*)&out[(size_t)(row + 8) * CC + col] = v1;
            }
        }
    } else {
        // epilogue: bias + relu, emit LN partials (s1, s2, s3=sum x*gw)
        __syncthreads();                       // stage smem free for reuse
        float* spart = (float*)sm;             // [128][4][3]
#pragma unroll
        for (int mt = 0; mt < 4; mt++) {
            float sA0 = 0.f, sA1 = 0.f, sA2 = 0.f;
            float sB0 = 0.f, sB1 = 0.f, sB2 = 0.f;
#pragma unroll
            for (int nt = 0; nt < 4; nt++) {
                int col = n0 + warp_n * 32 + nt * 8 + tig * 2;
                float b0 = __ldg(&bias[col]);
                float b1 = __ldg(&bias[col + 1]);
                float g0 = __ldg(&gw[col]);
                float g1 = __ldg(&gw[col + 1]);
                float x0 = fmaxf(c[mt][nt][0] + b0, 0.f);
                float x1 = fmaxf(c[mt][nt][1] + b1, 0.f);
                float y0 = fmaxf(c[mt][nt][2] + b0, 0.f);
                float y1 = fmaxf(c[mt][nt][3] + b1, 0.f);
                sA0 += x0 + x1; sA1 += x0 * x0 + x1 * x1; sA2 += x0 * g0 + x1 * g1;
                sB0 += y0 + y1; sB1 += y0 * y0 + y1 * y1; sB2 += y0 * g0 + y1 * g1;
            }
#pragma unroll
            for (int o = 1; o <= 2; o <<= 1) {
                sA0 += __shfl_xor_sync(0xffffffffu, sA0, o);
                sA1 += __shfl_xor_sync(0xffffffffu, sA1, o);
                sA2 += __shfl_xor_sync(0xffffffffu, sA2, o);
                sB0 += __shfl_xor_sync(0xffffffffu, sB0, o);
                sB1 += __shfl_xor_sync(0xffffffffu, sB1, o);
                sB2 += __shfl_xor_sync(0xffffffffu, sB2, o);
            }
            if (tig == 0) {
                int rA = warp_m * 64 + mt * 16 + gid;
                float* pA = spart + (rA * 4 + warp_n) * 3;
                pA[0] = sA0; pA[1] = sA1; pA[2] = sA2;
                float* pB = spart + ((rA + 8) * 4 + warp_n) * 3;
                pB[0] = sB0; pB[1] = sB1; pB[2] = sB2;
            }
        }
        __syncthreads();
        if (tid < 128) {
            float t0s = 0.f, t1s = 0.f, t2s = 0.f;
#pragma unroll
            for (int wn = 0; wn < 4; wn++) {
                const float* p = spart + (tid * 4 + wn) * 3;
                t0s += p[0]; t1s += p[1]; t2s += p[2];
            }
            size_t row = (size_t)(m0 + tid);
            float* dst = part + (row * 4 + (n0 >> 7)) * 4;
            dst[0] = t0s; dst[1] = t1s; dst[2] = t2s;
        }
    }
}

// ============ MEGA: conv1 (blocks [0,1024)) | regulate (rest) ===============
__global__ void __launch_bounds__(256, 2) mega_kernel(const __half* __restrict__ A,
                                                      const __half* __restrict__ Wt,
                                                      const float* __restrict__ bias,
                                                      float* __restrict__ out,
                                                      const float* __restrict__ batch,
                                                      const int* __restrict__ cum,
                                                      float* __restrict__ padded)
{
    __shared__ ConvSmem sm;            // 48KB; sc aliases it in the reg branch
    int tid = threadIdx.x;

    if (blockIdx.x < CONV_BLKS) {
        int m0 = (blockIdx.x >> 2) * BM;
        int n0 = (blockIdx.x & 3) * BN;
        conv_tile<false>(&sm, A, Wt, bias, out, nullptr, nullptr, m0, n0);
    } else {
        int* sc = (int*)&sm;           // 4KB overlay (disjoint branch)
        int r  = blockIdx.x - CONV_BLKS;
        int b  = r >> 7;
        int f0 = (r & 127) * 32;
        const int* crow = cum + (size_t)b * TT;
#pragma unroll
        for (int j = 0; j < 4; j++) sc[tid + 256 * j] = crow[tid + 256 * j];
        __syncthreads();
        int total = sc[TT - 1];
        int warp = tid >> 5, lane = tid & 31;
        float* outb = padded + (size_t)b * LMAX * CC;
        const float* inb = batch + (size_t)b * TT * CC;
#pragma unroll
        for (int qq = 0; qq < 4; qq++) {
            int f = f0 + warp * 4 + qq;
            float4* dst = (float4*)(outb + (size_t)f * CC);
            if (f < total) {
                int lo = 0, hi = TT;
                while (lo < hi) {
                    int mid = (lo + hi) >> 1;
                    if (sc[mid] <= f) lo = mid + 1; else hi = mid;
                }
                const float4* src = (const float4*)(inb + (size_t)lo * CC);
#pragma unroll
                for (int u = 0; u < 4; u++) dst[lane + 32 * u] = src[lane + 32 * u];
            } else {
                float4 z = make_float4(0.f, 0.f, 0.f, 0.f);
#pragma unroll
                for (int u = 0; u < 4; u++) dst[lane + 32 * u] = z;
            }
        }
    }
}

// ---------------- conv2: conv-as-GEMM with fused LN-partial epilogue --------
__global__ void __launch_bounds__(256, 2) conv2_kernel(const __half* __restrict__ A,
                                                       const __half* __restrict__ Wt,
                                                       const float* __restrict__ bias,
                                                       const float* __restrict__ gw,
                                                       float* __restrict__ part)
{
    __shared__ ConvSmem sm;
    conv_tile<true>(&sm, A, Wt, bias, nullptr, gw, part,
                    blockIdx.x * BM, blockIdx.y * BN);
}

// ---------------- finish: combine partials -> pred --------------------------
__global__ void __launch_bounds__(128) finish_kernel(const float* __restrict__ part,
                                                     const float* __restrict__ sc,
                                                     const float* __restrict__ lb,
                                                     const int* __restrict__ lens,
                                                     float* __restrict__ pred)
{
    int row = blockIdx.x * 128 + threadIdx.x;
    float s1 = 0.f, s2 = 0.f, s3 = 0.f;
#pragma unroll
    for (int nb = 0; nb < 4; nb++) {
        const float* p = part + ((size_t)row * 4 + nb) * 4;
        s1 += p[0]; s2 += p[1]; s3 += p[2];
    }
    float mean = s1 * (1.f / CC);
    float var  = s2 * (1.f / CC) - mean * mean;
    float r = rsqrtf(var + LN_EPS);
    float val = r * s3 - r * mean * sc[0] + sc[1] + lb[0];
    int b = row >> 10;
    int t = row & 1023;
    pred[row] = (t < lens[b]) ? val : 0.f;
}

// ---------------- LayerNorm over C=512, one block per row -------------------
// Reads fp32 normal order, writes fp16 slab-permuted (input to conv2).
__global__ void __launch_bounds__(128) ln_kernel(const float* __restrict__ x,
                                                 const float* __restrict__ g,
                                                 const float* __restrict__ beta,
                                                 __half* __restrict__ xo)
{
    size_t row = blockIdx.x;
    const float4* xr = (const float4*)(x + row * CC);
    int tid = threadIdx.x;
    float4 v = xr[tid];
    float s = v.x + v.y + v.z + v.w;
    float q = v.x * v.x + v.y * v.y + v.z * v.z + v.w * v.w;
#pragma unroll
    for (int o = 16; o > 0; o >>= 1) {
        s += __shfl_xor_sync(0xffffffffu, s, o);
        q += __shfl_xor_sync(0xffffffffu, q, o);
    }
    __shared__ float ss[4], sq[4];
    int w = tid >> 5, l = tid & 31;
    if (l == 0) { ss[w] = s; sq[w] = q; }
    __syncthreads();
    s = ss[0] + ss[1] + ss[2] + ss[3];
    q = sq[0] + sq[1] + sq[2] + sq[3];
    float mean = s * (1.f / CC);
    float var  = q * (1.f / CC) - mean * mean;
    float r = rsqrtf(var + LN_EPS);
    float4 gv = ((const float4*)g)[tid];
    float4 bv = ((const float4*)beta)[tid];
    float o0 = (v.x - mean) * r * gv.x + bv.x;
    float o1 = (v.y - mean) * r * gv.y + bv.y;
    float o2 = (v.z - mean) * r * gv.z + bv.z;
    float o3 = (v.w - mean) * r * gv.w + bv.w;
    int sl = tid >> 3;
    int p0 = (tid & 7) * 2;
    store_perm4(xo + row * CC + sl * 32, p0, o0, o1, o2, o3);
}

// ---------------- launch --------------------------------------------------
extern "C" void kernel_launch(void* const* d_in, const int* in_sizes, int n_in,
                              void* d_out, int out_size)
{
    const float* batch = (const float*)d_in[0];
    const int*   lens  = (const int*)d_in[1];
    const int*   durs  = (const int*)d_in[3];
    const float* w1    = (const float*)d_in[4];
    const float* b1    = (const float*)d_in[5];
    const float* g1    = (const float*)d_in[6];
    const float* be1   = (const float*)d_in[7];
    const float* w2    = (const float*)d_in[8];
    const float* b2    = (const float*)d_in[9];
    const float* g2    = (const float*)d_in[10];
    const float* be2   = (const float*)d_in[11];
    const float* lw    = (const float*)d_in[12];
    const float* lb    = (const float*)d_in[13];

    float* out    = (float*)d_out;
    float* padded = out;
    float* mel    = out + (size_t)BB * LMAX * CC;
    float* pred   = mel + BB;

    __half *bufA, *buf1h, *wt;
    float  *buf1, *partb, *gw, *sc;
    int    *cum;
    cudaGetSymbolAddress((void**)&bufA,  g_bufA);
    cudaGetSymbolAddress((void**)&buf1,  g_buf1);
    cudaGetSymbolAddress((void**)&buf1h, g_buf1h);
    cudaGetSymbolAddress((void**)&partb, g_part);
    cudaGetSymbolAddress((void**)&wt,    g_wt);
    cudaGetSymbolAddress((void**)&cum,   g_cum);
    cudaGetSymbolAddress((void**)&gw,    g_gw);
    cudaGetSymbolAddress((void**)&sc,    g_sc);
    __half* wt2 = wt + (size_t)KK * CC * CC;

    pre_kernel<<<RND_BLKS + 2 * WT_BLKS + BB + 1, 256>>>(
        (const float4*)batch, bufA, w1, w2, wt, wt2, durs, lens, cum, mel,
        g2, be2, lw, gw, sc);

    mega_kernel<<<CONV_BLKS + REG_BLKS, 256>>>(
        bufA, wt, b1, buf1, batch, cum, padded);

    ln_kernel<<<BT, 128>>>(buf1, g1, be1, buf1h);
    conv2_kernel<<<dim3(BT / BM, CC / BN), 256>>>(buf1h, wt2, b2, gw, partb);
    finish_kernel<<<BT / 128, 128>>>(partb, sc, lb, lens, pred);
}